// round 3
// baseline (speedup 1.0000x reference)
#include <cuda_runtime.h>
#include <cuda_fp16.h>

#define NPTS  100000
#define NPAD3 100032          // 1563 * 64, covers k3's unguarded cp.async row reads
#define CIN   96
#define CHID  576
#define COUT  96

// ---------------- device scratch ----------------
__device__ __align__(16) signed char g_feats8[(size_t)NPTS * CIN];     // feats s8 (exact)
__device__ __align__(16) signed char g_w1t8[(size_t)CHID * CIN];       // w1^T s8 [n][k]
__device__ __align__(16) __half      g_w3t [(size_t)COUT * CHID];      // w3^T f16 [n][k]
__device__ __align__(16) signed char g_w3t8[(size_t)COUT * CHID];      // w3^T s8  [n][k]
__device__ __align__(16) __half      g_x1s [(size_t)NPTS * CHID];      // x1*256 (ints 0..1536)
__device__ __align__(16) __half      g_x2h [(size_t)NPAD3 * CHID];     // x2 hi (fp16 rn)
__device__ __align__(16) signed char g_x2l [(size_t)NPAD3 * CHID];     // (x2-hi)*65536 as s8

__device__ __forceinline__ float clamp128f(float x) { return fminf(fmaxf(x, -128.0f), 128.0f); }
__device__ __forceinline__ float relu6f(float x)    { return fminf(fmaxf(x, 0.0f), 6.0f); }
__device__ __forceinline__ unsigned ld32(const void* p) { return *reinterpret_cast<const unsigned*>(p); }

__device__ __forceinline__ void mma16816(float* c, const unsigned* a, const unsigned* b) {
    asm volatile(
        "mma.sync.aligned.m16n8k16.row.col.f32.f16.f16.f32 "
        "{%0,%1,%2,%3}, {%4,%5,%6,%7}, {%8,%9}, {%0,%1,%2,%3};\n"
        : "+f"(c[0]), "+f"(c[1]), "+f"(c[2]), "+f"(c[3])
        : "r"(a[0]), "r"(a[1]), "r"(a[2]), "r"(a[3]), "r"(b[0]), "r"(b[1]));
}
__device__ __forceinline__ void imma16832(int* c, const unsigned* a, const unsigned* b) {
    asm volatile(
        "mma.sync.aligned.m16n8k32.row.col.s32.s8.s8.s32 "
        "{%0,%1,%2,%3}, {%4,%5,%6,%7}, {%8,%9}, {%0,%1,%2,%3};\n"
        : "+r"(c[0]), "+r"(c[1]), "+r"(c[2]), "+r"(c[3])
        : "r"(a[0]), "r"(a[1]), "r"(a[2]), "r"(a[3]), "r"(b[0]), "r"(b[1]));
}
__device__ __forceinline__ void cp16(void* s, const void* g) {
    unsigned sa = (unsigned)__cvta_generic_to_shared(s);
    asm volatile("cp.async.ca.shared.global [%0], [%1], 16;\n" :: "r"(sa), "l"(g));
}
__device__ __forceinline__ void cp8(void* s, const void* g) {
    unsigned sa = (unsigned)__cvta_generic_to_shared(s);
    asm volatile("cp.async.ca.shared.global [%0], [%1], 8;\n" :: "r"(sa), "l"(g));
}

// ---------------------------------------------------------------------------
// Kernel 0: conversions. feats -> s8, w1^T -> s8, w3^T -> f16 + s8.
// ---------------------------------------------------------------------------
__global__ __launch_bounds__(256) void k_convert(
    const float* __restrict__ feats, const float* __restrict__ w1,
    const float* __restrict__ w3)
{
    const size_t i = (size_t)blockIdx.x * blockDim.x + threadIdx.x;
    if (i < (size_t)NPTS * CIN)
        g_feats8[i] = (signed char)__float2int_rn(feats[i]);
    if (i < (size_t)CIN * CHID) {   // 55296
        const int n = (int)(i / CIN), k = (int)(i % CIN);
        g_w1t8[i] = (signed char)__float2int_rn(w1[(size_t)k * CHID + n]);
        const int n3 = (int)(i / CHID), k3 = (int)(i % CHID);
        const float w = w3[(size_t)k3 * COUT + n3];
        g_w3t[i]  = __float2half_rn(w);
        g_w3t8[i] = (signed char)__float2int_rn(w);
    }
}

// ---------------------------------------------------------------------------
// Kernel 1: x1s = 256 * relu6(clamp(requant(feats @ w1 + b1, s1)))  -- s8 IMMA
// BM=128, BN=64, K=96 (3 k-steps of 32). 256 thr, 8 warps (4m x 2n), warp 32x32.
// ---------------------------------------------------------------------------
#define SA1 112   // A/B row stride bytes (96 + 16 pad): conflict-free frag loads
__global__ __launch_bounds__(256) void k1_expand(
    const float* __restrict__ b1, const float* __restrict__ s1)
{
    __shared__ __align__(16) signed char As[128 * SA1];
    __shared__ __align__(16) signed char Bs[64 * SA1];

    const int n0 = blockIdx.x * 128;
    const int h0 = blockIdx.y * 64;
    const int tid = threadIdx.x;

    // stage A: 128 rows x 96 B = 768 uint4 (3/thread)
#pragma unroll
    for (int p = 0; p < 3; p++) {
        const int idx = tid + p * 256;
        const int r = idx / 6, s = idx % 6;
        const int n = n0 + r;
        uint4 v = make_uint4(0u, 0u, 0u, 0u);
        if (n < NPTS) v = *reinterpret_cast<const uint4*>(g_feats8 + (size_t)n * CIN + s * 16);
        *reinterpret_cast<uint4*>(As + r * SA1 + s * 16) = v;
    }
    // stage B: 64 rows x 96 B = 384 uint4
#pragma unroll
    for (int p = 0; p < 2; p++) {
        const int idx = tid + p * 256;
        if (idx < 384) {
            const int r = idx / 6, s = idx % 6;
            *reinterpret_cast<uint4*>(Bs + r * SA1 + s * 16) =
                *reinterpret_cast<const uint4*>(g_w1t8 + (size_t)(h0 + r) * CIN + s * 16);
        }
    }
    __syncthreads();

    const int lane = tid & 31, wid = tid >> 5;
    const int wm = wid & 3, wn = wid >> 2;
    const int gid = lane >> 2, tig = lane & 3;

    int acc[2][4][4];
#pragma unroll
    for (int mi = 0; mi < 2; mi++)
#pragma unroll
        for (int ni = 0; ni < 4; ni++)
#pragma unroll
            for (int q = 0; q < 4; q++) acc[mi][ni][q] = 0;

#pragma unroll
    for (int ks = 0; ks < 3; ks++) {
        const int k0 = ks * 32;
        unsigned a[2][4], b[4][2];
#pragma unroll
        for (int mi = 0; mi < 2; mi++) {
            const signed char* pa = As + (wm * 32 + mi * 16 + gid) * SA1 + k0 + tig * 4;
            a[mi][0] = ld32(pa);
            a[mi][1] = ld32(pa + 8 * SA1);
            a[mi][2] = ld32(pa + 16);
            a[mi][3] = ld32(pa + 8 * SA1 + 16);
        }
#pragma unroll
        for (int ni = 0; ni < 4; ni++) {
            const signed char* pb = Bs + (wn * 32 + ni * 8 + gid) * SA1 + k0 + tig * 4;
            b[ni][0] = ld32(pb);
            b[ni][1] = ld32(pb + 16);
        }
#pragma unroll
        for (int mi = 0; mi < 2; mi++)
#pragma unroll
            for (int ni = 0; ni < 4; ni++)
                imma16832(acc[mi][ni], a[mi], b[ni]);
    }

#pragma unroll
    for (int ni = 0; ni < 4; ni++) {
        const int c = h0 + wn * 32 + ni * 8 + 2 * tig;
        const float bb0 = __ldg(b1 + c),     bb1 = __ldg(b1 + c + 1);
        const float m0  = rintf(__ldg(s1 + c)) * 256.0f;
        const float m1  = rintf(__ldg(s1 + c + 1)) * 256.0f;
#pragma unroll
        for (int mi = 0; mi < 2; mi++) {
            const int r = n0 + wm * 32 + mi * 16 + gid;
#pragma unroll
            for (int h = 0; h < 2; h++) {
                const int rr = r + h * 8;
                if (rr < NPTS) {
                    const float t0 = ((float)acc[mi][ni][2 * h]     + bb0) * m0;
                    const float t1 = ((float)acc[mi][ni][2 * h + 1] + bb1) * m1;
                    const float v0 = relu6f(clamp128f(t0 * (1.0f / 65536.0f)));
                    const float v1 = relu6f(clamp128f(t1 * (1.0f / 65536.0f)));
                    *reinterpret_cast<__half2*>(g_x1s + (size_t)rr * CHID + c) =
                        __halves2half2(__float2half_rn(v0 * 256.0f),
                                       __float2half_rn(v1 * 256.0f));
                }
            }
        }
    }
}

// ---------------------------------------------------------------------------
// Kernel 2: depthwise 3x3 sparse conv. x1s fp16 -> x2 (hi fp16, lo s8).
// ---------------------------------------------------------------------------
__global__ __launch_bounds__(288) void k2_dw(
    const int* __restrict__ nbr, const float* __restrict__ w2,
    const float* __restrict__ b2, const float* __restrict__ s2)
{
    __shared__ int nbs[9 * 64];

    const int n0 = blockIdx.x * 64;
    const int c  = 2 * threadIdx.x;

    float2 wv[9];
#pragma unroll
    for (int k = 0; k < 9; k++) {
        wv[k].x = __ldg(w2 + k * CHID + c);
        wv[k].y = __ldg(w2 + k * CHID + c + 1);
    }
    const float bb0 = __ldg(b2 + c),     bb1 = __ldg(b2 + c + 1);
    const float m0  = rintf(__ldg(s2 + c)) * 256.0f;
    const float m1  = rintf(__ldg(s2 + c + 1)) * 256.0f;

    for (int idx = threadIdx.x; idx < 9 * 64; idx += 288) {
        const int k = idx / 64, j = idx % 64;
        const int n = n0 + j;
        nbs[idx] = (n < NPTS) ? __ldg(nbr + (size_t)k * NPTS + n) : -1;
    }
    __syncthreads();

    const int jmax = min(64, NPTS - n0);
    for (int j = 0; j < jmax; j++) {
        float a0 = 0.0f, a1 = 0.0f;
#pragma unroll
        for (int k = 0; k < 9; k++) {
            const int nb = nbs[k * 64 + j];      // uniform across block
            if (nb >= 0) {
                const __half2 h = *reinterpret_cast<const __half2*>(
                    g_x1s + (size_t)nb * CHID + c);
                const float2 f = __half22float2(h);
                a0 = fmaf(f.x, wv[k].x, a0);
                a1 = fmaf(f.y, wv[k].y, a1);
            }
        }
        const float d0 = a0 * (1.0f / 256.0f) + bb0;
        const float d1 = a1 * (1.0f / 256.0f) + bb1;
        const float v0 = relu6f(clamp128f(d0 * m0 * (1.0f / 65536.0f)));
        const float v1 = relu6f(clamp128f(d1 * m1 * (1.0f / 65536.0f)));
        const __half h0 = __float2half_rn(v0), h1 = __float2half_rn(v1);
        int l0 = __float2int_rn((v0 - __half2float(h0)) * 65536.0f);
        int l1 = __float2int_rn((v1 - __half2float(h1)) * 65536.0f);
        l0 = max(-128, min(127, l0));
        l1 = max(-128, min(127, l1));
        const size_t o = (size_t)(n0 + j) * CHID + c;
        *reinterpret_cast<__half2*>(g_x2h + o) = __halves2half2(h0, h1);
        g_x2l[o]     = (signed char)l0;
        g_x2l[o + 1] = (signed char)l1;
    }
}

// ---------------------------------------------------------------------------
// Kernel 3: out = rm*clamp(requant(x2 @ w3 + b3, s3)) + rr*feats
// x2 = x2h (fp16 HMMA) + x2l/65536 (s8 IMMA). BM=64, BN=96, BK=32, 18 iters,
// cp.async 2-stage double buffer. 256 thr, 8 warps (2m x 4n), warp 32x24.
// ---------------------------------------------------------------------------
#define NIT3 18
#define SH3  40   // fp16 tile row stride in halves (32 + 8 pad)
#define SL3  48   // s8 tile row stride in bytes (32 + 16 pad)
__global__ __launch_bounds__(256) void k3_project(
    const float* __restrict__ feats, const float* __restrict__ b3,
    const float* __restrict__ s3,    const float* __restrict__ s_main,
    const float* __restrict__ s_res, float* __restrict__ out)
{
    __shared__ __align__(16) __half      AH[2][64 * SH3];
    __shared__ __align__(16) signed char AL[2][64 * SL3];
    __shared__ __align__(16) __half      BH[2][96 * SH3];
    __shared__ __align__(16) signed char BL[2][96 * SL3];

    const int n0  = blockIdx.x * 64;
    const int tid = threadIdx.x;
    const int lane = tid & 31, wid = tid >> 5;
    const int wm = wid & 1, wn = wid >> 1;
    const int gid = lane >> 2, tig = lane & 3;

    float ach[2][3][4];
    int   acl[2][3][4];
#pragma unroll
    for (int mi = 0; mi < 2; mi++)
#pragma unroll
        for (int ni = 0; ni < 3; ni++)
#pragma unroll
            for (int q = 0; q < 4; q++) { ach[mi][ni][q] = 0.0f; acl[mi][ni][q] = 0; }

    auto stage = [&](int it, int b) {
        const int k0 = it * 32;
        {   // A: 64 rows, 32 halves (2 x uint4... 256 x cp16) + 32 bytes (256 x cp8)
            const int r = tid >> 2, s = tid & 3;
            cp16(&AH[b][r * SH3 + s * 8], g_x2h + (size_t)(n0 + r) * CHID + k0 + s * 8);
            cp8 (&AL[b][r * SL3 + s * 8], g_x2l + (size_t)(n0 + r) * CHID + k0 + s * 8);
        }
#pragma unroll
        for (int p = 0; p < 2; p++) {   // B: 96 rows -> 384 cp16 + 384 cp8
            const int idx = tid + p * 256;
            if (idx < 384) {
                const int r = idx >> 2, s = idx & 3;
                cp16(&BH[b][r * SH3 + s * 8], g_w3t  + (size_t)r * CHID + k0 + s * 8);
                cp8 (&BL[b][r * SL3 + s * 8], g_w3t8 + (size_t)r * CHID + k0 + s * 8);
            }
        }
        asm volatile("cp.async.commit_group;\n");
    };

    stage(0, 0);

    for (int it = 0; it < NIT3; it++) {
        const int b = it & 1;
        if (it + 1 < NIT3) {
            stage(it + 1, b ^ 1);
            asm volatile("cp.async.wait_group 1;\n");
        } else {
            asm volatile("cp.async.wait_group 0;\n");
        }
        __syncthreads();

        // ---- hi plane: 2 HMMA k-steps of 16 ----
#pragma unroll
        for (int ks = 0; ks < 2; ks++) {
            const int kk = ks * 16;
            unsigned a[2][4], bb[3][2];
#pragma unroll
            for (int mi = 0; mi < 2; mi++) {
                const __half* pa = &AH[b][(wm * 32 + mi * 16 + gid) * SH3 + kk + 2 * tig];
                a[mi][0] = ld32(pa);
                a[mi][1] = ld32(pa + 8 * SH3);
                a[mi][2] = ld32(pa + 8);
                a[mi][3] = ld32(pa + 8 * SH3 + 8);
            }
#pragma unroll
            for (int ni = 0; ni < 3; ni++) {
                const __half* pb = &BH[b][(wn * 24 + ni * 8 + gid) * SH3 + kk + 2 * tig];
                bb[ni][0] = ld32(pb);
                bb[ni][1] = ld32(pb + 8);
            }
#pragma unroll
            for (int mi = 0; mi < 2; mi++)
#pragma unroll
                for (int ni = 0; ni < 3; ni++)
                    mma16816(ach[mi][ni], a[mi], bb[ni]);
        }
        // ---- lo plane: 1 IMMA k-step of 32 ----
        {
            unsigned a[2][4], bb[3][2];
#pragma unroll
            for (int mi = 0; mi < 2; mi++) {
                const signed char* pa = &AL[b][(wm * 32 + mi * 16 + gid) * SL3 + tig * 4];
                a[mi][0] = ld32(pa);
                a[mi][1] = ld32(pa + 8 * SL3);
                a[mi][2] = ld32(pa + 16);
                a[mi][3] = ld32(pa + 8 * SL3 + 16);
            }
#pragma unroll
            for (int ni = 0; ni < 3; ni++) {
                const signed char* pb = &BL[b][(wn * 24 + ni * 8 + gid) * SL3 + tig * 4];
                bb[ni][0] = ld32(pb);
                bb[ni][1] = ld32(pb + 16);
            }
#pragma unroll
            for (int mi = 0; mi < 2; mi++)
#pragma unroll
                for (int ni = 0; ni < 3; ni++)
                    imma16832(acl[mi][ni], a[mi], bb[ni]);
        }
        __syncthreads();
    }

    const float rm = rintf(__ldg(s_main)) * 256.0f;
    const float rr = rintf(__ldg(s_res)) * 256.0f;

#pragma unroll
    for (int ni = 0; ni < 3; ni++) {
        const int c = wn * 24 + ni * 8 + 2 * tig;
        const float bb0 = __ldg(b3 + c),     bb1 = __ldg(b3 + c + 1);
        const float m0  = rintf(__ldg(s3 + c)) * 256.0f;
        const float m1  = rintf(__ldg(s3 + c + 1)) * 256.0f;
#pragma unroll
        for (int mi = 0; mi < 2; mi++) {
            const int r = n0 + wm * 32 + mi * 16 + gid;
#pragma unroll
            for (int h = 0; h < 2; h++) {
                const int rr_ = r + h * 8;
                if (rr_ < NPTS) {
                    const float a0 = ach[mi][ni][2 * h]     + (float)acl[mi][ni][2 * h]     * (1.0f / 65536.0f);
                    const float a1 = ach[mi][ni][2 * h + 1] + (float)acl[mi][ni][2 * h + 1] * (1.0f / 65536.0f);
                    const float v0 = clamp128f((a0 + bb0) * m0 * (1.0f / 65536.0f));
                    const float v1 = clamp128f((a1 + bb1) * m1 * (1.0f / 65536.0f));
                    const float2 f = *reinterpret_cast<const float2*>(
                        feats + (size_t)rr_ * CIN + c);
                    float2 o;
                    o.x = rm * v0 + rr * f.x;
                    o.y = rm * v1 + rr * f.y;
                    *reinterpret_cast<float2*>(out + (size_t)rr_ * COUT + c) = o;
                }
            }
        }
    }
}

// ---------------------------------------------------------------------------
extern "C" void kernel_launch(void* const* d_in, const int* in_sizes, int n_in,
                              void* d_out, int out_size)
{
    const float* feats = (const float*)d_in[0];
    const int*   nbr   = (const int*)  d_in[1];
    const float* w1    = (const float*)d_in[2];
    const float* b1    = (const float*)d_in[3];
    const float* w2    = (const float*)d_in[4];
    const float* b2    = (const float*)d_in[5];
    const float* w3    = (const float*)d_in[6];
    const float* b3    = (const float*)d_in[7];
    const float* s1    = (const float*)d_in[8];
    const float* s2    = (const float*)d_in[9];
    const float* s3    = (const float*)d_in[10];
    const float* smain = (const float*)d_in[11];
    const float* sres  = (const float*)d_in[12];
    float* out = (float*)d_out;

    const int cvt_blocks = (int)(((size_t)NPTS * CIN + 255) / 256);
    k_convert<<<cvt_blocks, 256>>>(feats, w1, w3);

    k1_expand <<<dim3((NPTS + 127) / 128, CHID / 64), 256>>>(b1, s1);
    k2_dw     <<<(NPTS + 63) / 64, 288>>>(nbr, w2, b2, s2);
    k3_project<<<(NPTS + 63) / 64, 256>>>(feats, b3, s3, smain, sres, out);
}

// round 4
// speedup vs baseline: 1.1271x; 1.1271x over previous
#include <cuda_runtime.h>
#include <cuda_fp16.h>

#define NPTS  100000
#define NPAD3 100032          // 1563 * 64, covers k3's unguarded cp.async row reads
#define CIN   96
#define CHID  576
#define COUT  96

// ---------------- device scratch ----------------
__device__ __align__(16) signed char g_feats8[(size_t)NPTS * CIN];     // feats s8 (exact)
__device__ __align__(16) signed char g_w1t8[(size_t)CHID * CIN];       // w1^T s8 [n][k]
__device__ __align__(16) __half      g_w3t [(size_t)COUT * CHID];      // w3^T f16 [n][k] (exact)
__device__ __align__(16) __half      g_x1s [(size_t)NPTS * CHID];      // x1*256 (ints 0..1536)
__device__ __align__(16) __half      g_x2h [(size_t)NPAD3 * CHID];     // x2 hi (fp16 rn)
__device__ __align__(16) __half      g_x2l [(size_t)NPAD3 * CHID];     // x2 - hi (fp16, exact)

__device__ __forceinline__ float clamp128f(float x) { return fminf(fmaxf(x, -128.0f), 128.0f); }
__device__ __forceinline__ float relu6f(float x)    { return fminf(fmaxf(x, 0.0f), 6.0f); }
__device__ __forceinline__ unsigned ld32(const void* p) { return *reinterpret_cast<const unsigned*>(p); }

__device__ __forceinline__ void mma16816(float* c, const unsigned* a, const unsigned* b) {
    asm volatile(
        "mma.sync.aligned.m16n8k16.row.col.f32.f16.f16.f32 "
        "{%0,%1,%2,%3}, {%4,%5,%6,%7}, {%8,%9}, {%0,%1,%2,%3};\n"
        : "+f"(c[0]), "+f"(c[1]), "+f"(c[2]), "+f"(c[3])
        : "r"(a[0]), "r"(a[1]), "r"(a[2]), "r"(a[3]), "r"(b[0]), "r"(b[1]));
}
__device__ __forceinline__ void imma16832(int* c, const unsigned* a, const unsigned* b) {
    asm volatile(
        "mma.sync.aligned.m16n8k32.row.col.s32.s8.s8.s32 "
        "{%0,%1,%2,%3}, {%4,%5,%6,%7}, {%8,%9}, {%0,%1,%2,%3};\n"
        : "+r"(c[0]), "+r"(c[1]), "+r"(c[2]), "+r"(c[3])
        : "r"(a[0]), "r"(a[1]), "r"(a[2]), "r"(a[3]), "r"(b[0]), "r"(b[1]));
}
__device__ __forceinline__ void cp16(void* s, const void* g) {
    unsigned sa = (unsigned)__cvta_generic_to_shared(s);
    asm volatile("cp.async.ca.shared.global [%0], [%1], 16;\n" :: "r"(sa), "l"(g));
}

// ---------------------------------------------------------------------------
// Kernel 0: conversions. feats -> s8, w1^T -> s8, w3^T -> f16.
// ---------------------------------------------------------------------------
__global__ __launch_bounds__(256) void k_convert(
    const float* __restrict__ feats, const float* __restrict__ w1,
    const float* __restrict__ w3)
{
    const size_t i = (size_t)blockIdx.x * blockDim.x + threadIdx.x;
    if (i < (size_t)NPTS * CIN)
        g_feats8[i] = (signed char)__float2int_rn(feats[i]);
    if (i < (size_t)CIN * CHID) {   // 55296
        const int n = (int)(i / CIN), k = (int)(i % CIN);
        g_w1t8[i] = (signed char)__float2int_rn(w1[(size_t)k * CHID + n]);
        const int n3 = (int)(i / CHID), k3 = (int)(i % CHID);
        g_w3t[i] = __float2half_rn(w3[(size_t)k3 * COUT + n3]);
    }
}

// ---------------------------------------------------------------------------
// Kernel 1: x1s = 256 * relu6(clamp(requant(feats @ w1 + b1, s1)))  -- s8 IMMA
// BM=128, BN=64, K=96 (3 k-steps of 32). 256 thr, 8 warps (4m x 2n), warp 32x32.
// ---------------------------------------------------------------------------
#define SA1 112   // A/B row stride bytes (96 + 16 pad): conflict-free frag loads
__global__ __launch_bounds__(256) void k1_expand(
    const float* __restrict__ b1, const float* __restrict__ s1)
{
    __shared__ __align__(16) signed char As[128 * SA1];
    __shared__ __align__(16) signed char Bs[64 * SA1];

    const int n0 = blockIdx.x * 128;
    const int h0 = blockIdx.y * 64;
    const int tid = threadIdx.x;

    // stage A: 128 rows x 96 B = 768 uint4 (3/thread)
#pragma unroll
    for (int p = 0; p < 3; p++) {
        const int idx = tid + p * 256;
        const int r = idx / 6, s = idx % 6;
        const int n = n0 + r;
        uint4 v = make_uint4(0u, 0u, 0u, 0u);
        if (n < NPTS) v = *reinterpret_cast<const uint4*>(g_feats8 + (size_t)n * CIN + s * 16);
        *reinterpret_cast<uint4*>(As + r * SA1 + s * 16) = v;
    }
    // stage B: 64 rows x 96 B = 384 uint4
#pragma unroll
    for (int p = 0; p < 2; p++) {
        const int idx = tid + p * 256;
        if (idx < 384) {
            const int r = idx / 6, s = idx % 6;
            *reinterpret_cast<uint4*>(Bs + r * SA1 + s * 16) =
                *reinterpret_cast<const uint4*>(g_w1t8 + (size_t)(h0 + r) * CIN + s * 16);
        }
    }
    __syncthreads();

    const int lane = tid & 31, wid = tid >> 5;
    const int wm = wid & 3, wn = wid >> 2;
    const int gid = lane >> 2, tig = lane & 3;

    int acc[2][4][4];
#pragma unroll
    for (int mi = 0; mi < 2; mi++)
#pragma unroll
        for (int ni = 0; ni < 4; ni++)
#pragma unroll
            for (int q = 0; q < 4; q++) acc[mi][ni][q] = 0;

#pragma unroll
    for (int ks = 0; ks < 3; ks++) {
        const int k0 = ks * 32;
        unsigned a[2][4], b[4][2];
#pragma unroll
        for (int mi = 0; mi < 2; mi++) {
            const signed char* pa = As + (wm * 32 + mi * 16 + gid) * SA1 + k0 + tig * 4;
            a[mi][0] = ld32(pa);
            a[mi][1] = ld32(pa + 8 * SA1);
            a[mi][2] = ld32(pa + 16);
            a[mi][3] = ld32(pa + 8 * SA1 + 16);
        }
#pragma unroll
        for (int ni = 0; ni < 4; ni++) {
            const signed char* pb = Bs + (wn * 32 + ni * 8 + gid) * SA1 + k0 + tig * 4;
            b[ni][0] = ld32(pb);
            b[ni][1] = ld32(pb + 16);
        }
#pragma unroll
        for (int mi = 0; mi < 2; mi++)
#pragma unroll
            for (int ni = 0; ni < 4; ni++)
                imma16832(acc[mi][ni], a[mi], b[ni]);
    }

#pragma unroll
    for (int ni = 0; ni < 4; ni++) {
        const int c = h0 + wn * 32 + ni * 8 + 2 * tig;
        const float bb0 = __ldg(b1 + c),     bb1 = __ldg(b1 + c + 1);
        const float m0  = rintf(__ldg(s1 + c)) * 256.0f;
        const float m1  = rintf(__ldg(s1 + c + 1)) * 256.0f;
#pragma unroll
        for (int mi = 0; mi < 2; mi++) {
            const int r = n0 + wm * 32 + mi * 16 + gid;
#pragma unroll
            for (int h = 0; h < 2; h++) {
                const int rr = r + h * 8;
                if (rr < NPTS) {
                    const float t0 = ((float)acc[mi][ni][2 * h]     + bb0) * m0;
                    const float t1 = ((float)acc[mi][ni][2 * h + 1] + bb1) * m1;
                    const float v0 = relu6f(clamp128f(t0 * (1.0f / 65536.0f)));
                    const float v1 = relu6f(clamp128f(t1 * (1.0f / 65536.0f)));
                    *reinterpret_cast<__half2*>(g_x1s + (size_t)rr * CHID + c) =
                        __halves2half2(__float2half_rn(v0 * 256.0f),
                                       __float2half_rn(v1 * 256.0f));
                }
            }
        }
    }
}

// ---------------------------------------------------------------------------
// Kernel 2: depthwise 3x3 sparse conv. x1s fp16 -> x2 (hi fp16 + lo fp16, exact).
// ---------------------------------------------------------------------------
__global__ __launch_bounds__(288) void k2_dw(
    const int* __restrict__ nbr, const float* __restrict__ w2,
    const float* __restrict__ b2, const float* __restrict__ s2)
{
    __shared__ int nbs[9 * 64];

    const int n0 = blockIdx.x * 64;
    const int c  = 2 * threadIdx.x;

    float2 wv[9];
#pragma unroll
    for (int k = 0; k < 9; k++) {
        wv[k].x = __ldg(w2 + k * CHID + c);
        wv[k].y = __ldg(w2 + k * CHID + c + 1);
    }
    const float bb0 = __ldg(b2 + c),     bb1 = __ldg(b2 + c + 1);
    const float m0  = rintf(__ldg(s2 + c)) * 256.0f;
    const float m1  = rintf(__ldg(s2 + c + 1)) * 256.0f;

    for (int idx = threadIdx.x; idx < 9 * 64; idx += 288) {
        const int k = idx / 64, j = idx % 64;
        const int n = n0 + j;
        nbs[idx] = (n < NPTS) ? __ldg(nbr + (size_t)k * NPTS + n) : -1;
    }
    __syncthreads();

    const int jmax = min(64, NPTS - n0);
    for (int j = 0; j < jmax; j++) {
        float a0 = 0.0f, a1 = 0.0f;
#pragma unroll
        for (int k = 0; k < 9; k++) {
            const int nb = nbs[k * 64 + j];      // uniform across block
            if (nb >= 0) {
                const __half2 h = *reinterpret_cast<const __half2*>(
                    g_x1s + (size_t)nb * CHID + c);
                const float2 f = __half22float2(h);
                a0 = fmaf(f.x, wv[k].x, a0);
                a1 = fmaf(f.y, wv[k].y, a1);
            }
        }
        const float d0 = a0 * (1.0f / 256.0f) + bb0;
        const float d1 = a1 * (1.0f / 256.0f) + bb1;
        const float v0 = relu6f(clamp128f(d0 * m0 * (1.0f / 65536.0f)));
        const float v1 = relu6f(clamp128f(d1 * m1 * (1.0f / 65536.0f)));
        const __half h0 = __float2half_rn(v0), h1 = __float2half_rn(v1);
        const __half l0 = __float2half_rn(v0 - __half2float(h0));   // exact (ulp fits)
        const __half l1 = __float2half_rn(v1 - __half2float(h1));
        const size_t o = (size_t)(n0 + j) * CHID + c;
        *reinterpret_cast<__half2*>(g_x2h + o) = __halves2half2(h0, h1);
        *reinterpret_cast<__half2*>(g_x2l + o) = __halves2half2(l0, l1);
    }
}

// ---------------------------------------------------------------------------
// Kernel 3: out = rm*clamp(requant((x2h+x2l) @ w3 + b3, s3)) + rr*feats
// BM=64, BN=96, BK=64, 9 iters. cp.async 2-stage double buffer, 1 sync/iter.
// 256 thr, 8 warps (2m x 4n), warp 32x24. Both planes HMMA into one fp32 acc.
// ---------------------------------------------------------------------------
#define NIT3 9
#define SH3  72   // fp16 tile row stride in halves (64 + 8): 36 words = 4 mod 32, conflict-free
__global__ __launch_bounds__(256) void k3_project(
    const float* __restrict__ feats, const float* __restrict__ b3,
    const float* __restrict__ s3,    const float* __restrict__ s_main,
    const float* __restrict__ s_res, float* __restrict__ out)
{
    __shared__ __align__(16) __half AH[2][64 * SH3];
    __shared__ __align__(16) __half AL[2][64 * SH3];
    __shared__ __align__(16) __half BS[2][96 * SH3];

    const int n0  = blockIdx.x * 64;
    const int tid = threadIdx.x;
    const int lane = tid & 31, wid = tid >> 5;
    const int wm = wid & 1, wn = wid >> 1;
    const int gid = lane >> 2, tig = lane & 3;

    float acc[2][3][4];
#pragma unroll
    for (int mi = 0; mi < 2; mi++)
#pragma unroll
        for (int ni = 0; ni < 3; ni++)
#pragma unroll
            for (int q = 0; q < 4; q++) acc[mi][ni][q] = 0.0f;

    auto stage = [&](int it, int b) {
        const int k0 = it * 64;
        // A hi+lo: 64 rows x 8 segs of 8 halves = 512 units -> 2 units/thread
#pragma unroll
        for (int p = 0; p < 2; p++) {
            const int idx = tid + p * 256;
            const int r = idx >> 3, s = idx & 7;
            const size_t g = (size_t)(n0 + r) * CHID + k0 + s * 8;
            cp16(&AH[b][r * SH3 + s * 8], g_x2h + g);
            cp16(&AL[b][r * SH3 + s * 8], g_x2l + g);
        }
        // B: 96 rows x 8 segs = 768 units -> 3/thread
#pragma unroll
        for (int p = 0; p < 3; p++) {
            const int idx = tid + p * 256;
            const int r = idx >> 3, s = idx & 7;
            cp16(&BS[b][r * SH3 + s * 8], g_w3t + (size_t)r * CHID + k0 + s * 8);
        }
        asm volatile("cp.async.commit_group;\n");
    };

    stage(0, 0);

    for (int it = 0; it < NIT3; it++) {
        const int b = it & 1;
        asm volatile("cp.async.wait_group 0;\n");
        __syncthreads();                        // data ready + prev compute on b^1 done
        if (it + 1 < NIT3) stage(it + 1, b ^ 1);  // overlaps with compute below

#pragma unroll
        for (int ks = 0; ks < 4; ks++) {
            const int kk = ks * 16;
            unsigned ah[2][4], al[2][4], bb[3][2];
#pragma unroll
            for (int mi = 0; mi < 2; mi++) {
                const int row = wm * 32 + mi * 16 + gid;
                const __half* ph = &AH[b][row * SH3 + kk + 2 * tig];
                ah[mi][0] = ld32(ph);
                ah[mi][1] = ld32(ph + 8 * SH3);
                ah[mi][2] = ld32(ph + 8);
                ah[mi][3] = ld32(ph + 8 * SH3 + 8);
                const __half* pl = &AL[b][row * SH3 + kk + 2 * tig];
                al[mi][0] = ld32(pl);
                al[mi][1] = ld32(pl + 8 * SH3);
                al[mi][2] = ld32(pl + 8);
                al[mi][3] = ld32(pl + 8 * SH3 + 8);
            }
#pragma unroll
            for (int ni = 0; ni < 3; ni++) {
                const __half* pb = &BS[b][(wn * 24 + ni * 8 + gid) * SH3 + kk + 2 * tig];
                bb[ni][0] = ld32(pb);
                bb[ni][1] = ld32(pb + 8);
            }
#pragma unroll
            for (int mi = 0; mi < 2; mi++)
#pragma unroll
                for (int ni = 0; ni < 3; ni++) {
                    mma16816(acc[mi][ni], ah[mi], bb[ni]);
                    mma16816(acc[mi][ni], al[mi], bb[ni]);
                }
        }
    }

    const float rm = rintf(__ldg(s_main)) * 256.0f;
    const float rr = rintf(__ldg(s_res)) * 256.0f;

#pragma unroll
    for (int ni = 0; ni < 3; ni++) {
        const int c = wn * 24 + ni * 8 + 2 * tig;
        const float bb0 = __ldg(b3 + c),     bb1 = __ldg(b3 + c + 1);
        const float m0  = rintf(__ldg(s3 + c)) * 256.0f;
        const float m1  = rintf(__ldg(s3 + c + 1)) * 256.0f;
#pragma unroll
        for (int mi = 0; mi < 2; mi++) {
            const int r = n0 + wm * 32 + mi * 16 + gid;
#pragma unroll
            for (int h = 0; h < 2; h++) {
                const int rr_ = r + h * 8;
                if (rr_ < NPTS) {
                    const float v0 = clamp128f((acc[mi][ni][2 * h]     + bb0) * m0 * (1.0f / 65536.0f));
                    const float v1 = clamp128f((acc[mi][ni][2 * h + 1] + bb1) * m1 * (1.0f / 65536.0f));
                    const float2 f = *reinterpret_cast<const float2*>(
                        feats + (size_t)rr_ * CIN + c);
                    float2 o;
                    o.x = rm * v0 + rr * f.x;
                    o.y = rm * v1 + rr * f.y;
                    *reinterpret_cast<float2*>(out + (size_t)rr_ * COUT + c) = o;
                }
            }
        }
    }
}

// ---------------------------------------------------------------------------
extern "C" void kernel_launch(void* const* d_in, const int* in_sizes, int n_in,
                              void* d_out, int out_size)
{
    const float* feats = (const float*)d_in[0];
    const int*   nbr   = (const int*)  d_in[1];
    const float* w1    = (const float*)d_in[2];
    const float* b1    = (const float*)d_in[3];
    const float* w2    = (const float*)d_in[4];
    const float* b2    = (const float*)d_in[5];
    const float* w3    = (const float*)d_in[6];
    const float* b3    = (const float*)d_in[7];
    const float* s1    = (const float*)d_in[8];
    const float* s2    = (const float*)d_in[9];
    const float* s3    = (const float*)d_in[10];
    const float* smain = (const float*)d_in[11];
    const float* sres  = (const float*)d_in[12];
    float* out = (float*)d_out;

    const int cvt_blocks = (int)(((size_t)NPTS * CIN + 255) / 256);
    k_convert<<<cvt_blocks, 256>>>(feats, w1, w3);

    k1_expand <<<dim3((NPTS + 127) / 128, CHID / 64), 256>>>(b1, s1);
    k2_dw     <<<(NPTS + 63) / 64, 288>>>(nbr, w2, b2, s2);
    k3_project<<<(NPTS + 63) / 64, 256>>>(feats, b3, s3, smain, sres, out);
}

// round 5
// speedup vs baseline: 1.2615x; 1.1192x over previous
#include <cuda_runtime.h>
#include <cuda_fp16.h>

#define NPTS  100000
#define CIN   96
#define CHID  576
#define COUT  96

// ---------------- device scratch ----------------
__device__ __align__(16) signed char g_feats8[(size_t)NPTS * CIN];     // feats s8 (exact)
__device__ __align__(16) signed char g_w1t8[(size_t)CHID * CIN];       // w1^T s8 [n][k]
__device__ __align__(16) __half      g_w3t [(size_t)COUT * CHID];      // w3^T f16 [n][k] (exact)
__device__ __align__(16) __half      g_x1s [(size_t)NPTS * CHID];      // x1*256 (ints 0..1536)

__device__ __forceinline__ float clamp128f(float x) { return fminf(fmaxf(x, -128.0f), 128.0f); }
__device__ __forceinline__ float relu6f(float x)    { return fminf(fmaxf(x, 0.0f), 6.0f); }
__device__ __forceinline__ unsigned ld32(const void* p) { return *reinterpret_cast<const unsigned*>(p); }

__device__ __forceinline__ void mma16816(float* c, const unsigned* a, const unsigned* b) {
    asm volatile(
        "mma.sync.aligned.m16n8k16.row.col.f32.f16.f16.f32 "
        "{%0,%1,%2,%3}, {%4,%5,%6,%7}, {%8,%9}, {%0,%1,%2,%3};\n"
        : "+f"(c[0]), "+f"(c[1]), "+f"(c[2]), "+f"(c[3])
        : "r"(a[0]), "r"(a[1]), "r"(a[2]), "r"(a[3]), "r"(b[0]), "r"(b[1]));
}
__device__ __forceinline__ void imma16832(int* c, const unsigned* a, const unsigned* b) {
    asm volatile(
        "mma.sync.aligned.m16n8k32.row.col.s32.s8.s8.s32 "
        "{%0,%1,%2,%3}, {%4,%5,%6,%7}, {%8,%9}, {%0,%1,%2,%3};\n"
        : "+r"(c[0]), "+r"(c[1]), "+r"(c[2]), "+r"(c[3])
        : "r"(a[0]), "r"(a[1]), "r"(a[2]), "r"(a[3]), "r"(b[0]), "r"(b[1]));
}
__device__ __forceinline__ void cp16(void* s, const void* g) {
    unsigned sa = (unsigned)__cvta_generic_to_shared(s);
    asm volatile("cp.async.ca.shared.global [%0], [%1], 16;\n" :: "r"(sa), "l"(g));
}

// ---------------------------------------------------------------------------
// Kernel 0: conversions. feats -> s8, w1^T -> s8, w3^T -> f16.
// ---------------------------------------------------------------------------
__global__ __launch_bounds__(256) void k_convert(
    const float* __restrict__ feats, const float* __restrict__ w1,
    const float* __restrict__ w3)
{
    const size_t i = (size_t)blockIdx.x * blockDim.x + threadIdx.x;
    if (i < (size_t)NPTS * CIN)
        g_feats8[i] = (signed char)__float2int_rn(feats[i]);
    if (i < (size_t)CIN * CHID) {   // 55296
        const int n = (int)(i / CIN), k = (int)(i % CIN);
        g_w1t8[i] = (signed char)__float2int_rn(w1[(size_t)k * CHID + n]);
        const int n3 = (int)(i / CHID), k3 = (int)(i % CHID);
        g_w3t[i] = __float2half_rn(w3[(size_t)k3 * COUT + n3]);
    }
}

// ---------------------------------------------------------------------------
// Kernel 1: x1s = 256 * relu6(clamp(requant(feats @ w1 + b1, s1)))  -- s8 IMMA
// BM=128, BN=64, K=96. 256 thr, 8 warps (4m x 2n), warp 32x32.
// ---------------------------------------------------------------------------
#define SA1 112
__global__ __launch_bounds__(256) void k1_expand(
    const float* __restrict__ b1, const float* __restrict__ s1)
{
    __shared__ __align__(16) signed char As[128 * SA1];
    __shared__ __align__(16) signed char Bs[64 * SA1];

    const int n0 = blockIdx.x * 128;
    const int h0 = blockIdx.y * 64;
    const int tid = threadIdx.x;

#pragma unroll
    for (int p = 0; p < 3; p++) {
        const int idx = tid + p * 256;
        const int r = idx / 6, s = idx % 6;
        const int n = n0 + r;
        uint4 v = make_uint4(0u, 0u, 0u, 0u);
        if (n < NPTS) v = *reinterpret_cast<const uint4*>(g_feats8 + (size_t)n * CIN + s * 16);
        *reinterpret_cast<uint4*>(As + r * SA1 + s * 16) = v;
    }
#pragma unroll
    for (int p = 0; p < 2; p++) {
        const int idx = tid + p * 256;
        if (idx < 384) {
            const int r = idx / 6, s = idx % 6;
            *reinterpret_cast<uint4*>(Bs + r * SA1 + s * 16) =
                *reinterpret_cast<const uint4*>(g_w1t8 + (size_t)(h0 + r) * CIN + s * 16);
        }
    }
    __syncthreads();

    const int lane = tid & 31, wid = tid >> 5;
    const int wm = wid & 3, wn = wid >> 2;
    const int gid = lane >> 2, tig = lane & 3;

    int acc[2][4][4];
#pragma unroll
    for (int mi = 0; mi < 2; mi++)
#pragma unroll
        for (int ni = 0; ni < 4; ni++)
#pragma unroll
            for (int q = 0; q < 4; q++) acc[mi][ni][q] = 0;

#pragma unroll
    for (int ks = 0; ks < 3; ks++) {
        const int k0 = ks * 32;
        unsigned a[2][4], b[4][2];
#pragma unroll
        for (int mi = 0; mi < 2; mi++) {
            const signed char* pa = As + (wm * 32 + mi * 16 + gid) * SA1 + k0 + tig * 4;
            a[mi][0] = ld32(pa);
            a[mi][1] = ld32(pa + 8 * SA1);
            a[mi][2] = ld32(pa + 16);
            a[mi][3] = ld32(pa + 8 * SA1 + 16);
        }
#pragma unroll
        for (int ni = 0; ni < 4; ni++) {
            const signed char* pb = Bs + (wn * 32 + ni * 8 + gid) * SA1 + k0 + tig * 4;
            b[ni][0] = ld32(pb);
            b[ni][1] = ld32(pb + 16);
        }
#pragma unroll
        for (int mi = 0; mi < 2; mi++)
#pragma unroll
            for (int ni = 0; ni < 4; ni++)
                imma16832(acc[mi][ni], a[mi], b[ni]);
    }

#pragma unroll
    for (int ni = 0; ni < 4; ni++) {
        const int c = h0 + wn * 32 + ni * 8 + 2 * tig;
        const float bb0 = __ldg(b1 + c),     bb1 = __ldg(b1 + c + 1);
        const float m0  = rintf(__ldg(s1 + c)) * 256.0f;
        const float m1  = rintf(__ldg(s1 + c + 1)) * 256.0f;
#pragma unroll
        for (int mi = 0; mi < 2; mi++) {
            const int r = n0 + wm * 32 + mi * 16 + gid;
#pragma unroll
            for (int h = 0; h < 2; h++) {
                const int rr = r + h * 8;
                if (rr < NPTS) {
                    const float t0 = ((float)acc[mi][ni][2 * h]     + bb0) * m0;
                    const float t1 = ((float)acc[mi][ni][2 * h + 1] + bb1) * m1;
                    const float v0 = relu6f(clamp128f(t0 * (1.0f / 65536.0f)));
                    const float v1 = relu6f(clamp128f(t1 * (1.0f / 65536.0f)));
                    *reinterpret_cast<__half2*>(g_x1s + (size_t)rr * CHID + c) =
                        __halves2half2(__float2half_rn(v0 * 256.0f),
                                       __float2half_rn(v1 * 256.0f));
                }
            }
        }
    }
}

// ---------------------------------------------------------------------------
// Kernel 23 (fused dw + project):
//   per block: 64 sites x 96 out cols.
//   per iter (9 x 64 channels): depthwise-gather+requant -> smem A (hi/lo fp16),
//   HMMA against cp.async double-buffered w3 tile; epilogue w/ residual.
// ---------------------------------------------------------------------------
#define NIT3 9
#define SH3  72   // A/B row stride in halves (64+8): 36 words == 4 mod 32, conflict-free

// dynamic smem layout (bytes):
#define OFF_BS   0                          // 2 * 96*72*2 = 27648
#define OFF_AH   27648                      // 64*72*2     =  9216
#define OFF_AL   36864                      //             =  9216
#define OFF_W2   46080                      // 9*576*4     = 20736
#define OFF_B2   66816                      // 576*4
#define OFF_M2   69120                      // 576*4
#define OFF_NB   71424                      // 9*64*4
#define SMEM_K23 73728

__global__ __launch_bounds__(256) void k23_fused(
    const int*   __restrict__ nbr,   const float* __restrict__ w2,
    const float* __restrict__ b2,    const float* __restrict__ s2,
    const float* __restrict__ feats, const float* __restrict__ b3,
    const float* __restrict__ s3,    const float* __restrict__ s_main,
    const float* __restrict__ s_res, float* __restrict__ out)
{
    extern __shared__ __align__(16) char smem[];
    __half* BS  = reinterpret_cast<__half*>(smem + OFF_BS);   // [2][96*SH3]
    __half* AH  = reinterpret_cast<__half*>(smem + OFF_AH);   // [64*SH3]
    __half* AL  = reinterpret_cast<__half*>(smem + OFF_AL);
    float*  w2f = reinterpret_cast<float*>(smem + OFF_W2);    // [9][576]
    float*  b2s = reinterpret_cast<float*>(smem + OFF_B2);
    float*  m2s = reinterpret_cast<float*>(smem + OFF_M2);
    int*    nbs = reinterpret_cast<int*>(smem + OFF_NB);      // [9][64]

    const int n0  = blockIdx.x * 64;
    const int tid = threadIdx.x;
    const int lane = tid & 31, wid = tid >> 5;
    const int wm = wid & 1, wn = wid >> 1;
    const int gid = lane >> 2, tig = lane & 3;

    // ---- one-time staging ----
    for (int idx = tid; idx < 9 * CHID; idx += 256) w2f[idx] = __ldg(w2 + idx);
    for (int idx = tid; idx < CHID; idx += 256) {
        b2s[idx] = __ldg(b2 + idx);
        m2s[idx] = rintf(__ldg(s2 + idx)) * 256.0f;
    }
    {
        const int k = tid / 64, j = tid & 63;       // tid<256 -> taps 0..3
        // stage all 9*64 neighbor ids
        for (int idx = tid; idx < 9 * 64; idx += 256) {
            const int kk = idx >> 6, jj = idx & 63;
            const int n = n0 + jj;
            nbs[idx] = (n < NPTS) ? __ldg(nbr + (size_t)kk * NPTS + n) : -1;
        }
        (void)k; (void)j;
    }
    // stage B chunk 0
#pragma unroll
    for (int p = 0; p < 3; p++) {
        const int idx = tid + p * 256;
        const int r = idx >> 3, s = idx & 7;
        cp16(&BS[r * SH3 + s * 8], g_w3t + (size_t)r * CHID + 0 + s * 8);
    }
    asm volatile("cp.async.commit_group;\n");
    __syncthreads();

    float acc[2][3][4];
#pragma unroll
    for (int mi = 0; mi < 2; mi++)
#pragma unroll
        for (int ni = 0; ni < 3; ni++)
#pragma unroll
            for (int q = 0; q < 4; q++) acc[mi][ni][q] = 0.0f;

    const int site = tid >> 2;          // 0..63
    const int cloc = (tid & 3) * 16;    // channel offset within 64-chunk

    for (int it = 0; it < NIT3; it++) {
        const int bsel = it & 1;
        __half* BSc = BS + bsel * (96 * SH3);

        // stage next B chunk (overlaps with dw compute below)
        if (it + 1 < NIT3) {
            const int k0n = (it + 1) * 64;
            __half* BSn = BS + (bsel ^ 1) * (96 * SH3);
#pragma unroll
            for (int p = 0; p < 3; p++) {
                const int idx = tid + p * 256;
                const int r = idx >> 3, s = idx & 7;
                cp16(&BSn[r * SH3 + s * 8], g_w3t + (size_t)r * CHID + k0n + s * 8);
            }
            asm volatile("cp.async.commit_group;\n");
        }

        // ---- depthwise compute for this 64-channel chunk ----
        const int kc = it * 64 + cloc;      // global channel base (16 ch)
        float accv[16];
#pragma unroll
        for (int q = 0; q < 16; q++) accv[q] = 0.0f;

#pragma unroll
        for (int tap = 0; tap < 9; tap++) {
            const int nb = nbs[tap * 64 + site];
            if (nb >= 0) {
                const uint4* px = reinterpret_cast<const uint4*>(
                    g_x1s + (size_t)nb * CHID + kc);
                const uint4 u0 = px[0], u1 = px[1];
                unsigned uu[8] = {u0.x, u0.y, u0.z, u0.w, u1.x, u1.y, u1.z, u1.w};
                const float* wf = w2f + tap * CHID + kc;
#pragma unroll
                for (int q = 0; q < 8; q++) {
                    const float2 f = __half22float2(*reinterpret_cast<__half2*>(&uu[q]));
                    accv[2 * q]     = fmaf(f.x, wf[2 * q],     accv[2 * q]);
                    accv[2 * q + 1] = fmaf(f.y, wf[2 * q + 1], accv[2 * q + 1]);
                }
            }
        }
        // requant -> hi/lo fp16
        unsigned hh[8], llv[8];
#pragma unroll
        for (int q = 0; q < 8; q++) {
#pragma unroll
            for (int e = 0; e < 2; e++) {
                const int j = 2 * q + e;
                const float d = accv[j] * (1.0f / 256.0f) + b2s[kc + j];
                const float v = relu6f(clamp128f(d * m2s[kc + j] * (1.0f / 65536.0f)));
                const __half h = __float2half_rn(v);
                const __half l = __float2half_rn(v - __half2float(h));
                if (e == 0) { hh[q] = (unsigned)__half_as_ushort(h); llv[q] = (unsigned)__half_as_ushort(l); }
                else        { hh[q] |= (unsigned)__half_as_ushort(h) << 16; llv[q] |= (unsigned)__half_as_ushort(l) << 16; }
            }
        }
        {
            __half* dh = AH + site * SH3 + cloc;
            __half* dl = AL + site * SH3 + cloc;
            *reinterpret_cast<uint4*>(dh)     = make_uint4(hh[0], hh[1], hh[2], hh[3]);
            *reinterpret_cast<uint4*>(dh + 8) = make_uint4(hh[4], hh[5], hh[6], hh[7]);
            *reinterpret_cast<uint4*>(dl)     = make_uint4(llv[0], llv[1], llv[2], llv[3]);
            *reinterpret_cast<uint4*>(dl + 8) = make_uint4(llv[4], llv[5], llv[6], llv[7]);
        }

        if (it + 1 < NIT3) asm volatile("cp.async.wait_group 1;\n");
        else               asm volatile("cp.async.wait_group 0;\n");
        __syncthreads();   // A tile written + B(it) arrived

        // ---- MMA over this chunk: 4 k-steps of 16, hi+lo planes ----
#pragma unroll
        for (int ks = 0; ks < 4; ks++) {
            const int kk = ks * 16;
            unsigned ah[2][4], al[2][4], bb[3][2];
#pragma unroll
            for (int mi = 0; mi < 2; mi++) {
                const int row = wm * 32 + mi * 16 + gid;
                const __half* ph = AH + row * SH3 + kk + 2 * tig;
                ah[mi][0] = ld32(ph);
                ah[mi][1] = ld32(ph + 8 * SH3);
                ah[mi][2] = ld32(ph + 8);
                ah[mi][3] = ld32(ph + 8 * SH3 + 8);
                const __half* pl = AL + row * SH3 + kk + 2 * tig;
                al[mi][0] = ld32(pl);
                al[mi][1] = ld32(pl + 8 * SH3);
                al[mi][2] = ld32(pl + 8);
                al[mi][3] = ld32(pl + 8 * SH3 + 8);
            }
#pragma unroll
            for (int ni = 0; ni < 3; ni++) {
                const __half* pb = BSc + (wn * 24 + ni * 8 + gid) * SH3 + kk + 2 * tig;
                bb[ni][0] = ld32(pb);
                bb[ni][1] = ld32(pb + 8);
            }
#pragma unroll
            for (int mi = 0; mi < 2; mi++)
#pragma unroll
                for (int ni = 0; ni < 3; ni++) {
                    mma16816(acc[mi][ni], ah[mi], bb[ni]);
                    mma16816(acc[mi][ni], al[mi], bb[ni]);
                }
        }
        __syncthreads();   // MMA done before next iter overwrites A tiles
    }

    const float rm = rintf(__ldg(s_main)) * 256.0f;
    const float rr = rintf(__ldg(s_res)) * 256.0f;

#pragma unroll
    for (int ni = 0; ni < 3; ni++) {
        const int c = wn * 24 + ni * 8 + 2 * tig;
        const float bb0 = __ldg(b3 + c),     bb1 = __ldg(b3 + c + 1);
        const float m0  = rintf(__ldg(s3 + c)) * 256.0f;
        const float m1  = rintf(__ldg(s3 + c + 1)) * 256.0f;
#pragma unroll
        for (int mi = 0; mi < 2; mi++) {
            const int r = n0 + wm * 32 + mi * 16 + gid;
#pragma unroll
            for (int h = 0; h < 2; h++) {
                const int rr_ = r + h * 8;
                if (rr_ < NPTS) {
                    const float v0 = clamp128f((acc[mi][ni][2 * h]     + bb0) * m0 * (1.0f / 65536.0f));
                    const float v1 = clamp128f((acc[mi][ni][2 * h + 1] + bb1) * m1 * (1.0f / 65536.0f));
                    const float2 f = *reinterpret_cast<const float2*>(
                        feats + (size_t)rr_ * CIN + c);
                    float2 o;
                    o.x = rm * v0 + rr * f.x;
                    o.y = rm * v1 + rr * f.y;
                    *reinterpret_cast<float2*>(out + (size_t)rr_ * COUT + c) = o;
                }
            }
        }
    }
}

// ---------------------------------------------------------------------------
extern "C" void kernel_launch(void* const* d_in, const int* in_sizes, int n_in,
                              void* d_out, int out_size)
{
    const float* feats = (const float*)d_in[0];
    const int*   nbr   = (const int*)  d_in[1];
    const float* w1    = (const float*)d_in[2];
    const float* b1    = (const float*)d_in[3];
    const float* w2    = (const float*)d_in[4];
    const float* b2    = (const float*)d_in[5];
    const float* w3    = (const float*)d_in[6];
    const float* b3    = (const float*)d_in[7];
    const float* s1    = (const float*)d_in[8];
    const float* s2    = (const float*)d_in[9];
    const float* s3    = (const float*)d_in[10];
    const float* smain = (const float*)d_in[11];
    const float* sres  = (const float*)d_in[12];
    float* out = (float*)d_out;

    static int smem_set = 0;
    if (!smem_set) {
        cudaFuncSetAttribute(k23_fused, cudaFuncAttributeMaxDynamicSharedMemorySize, SMEM_K23);
        smem_set = 1;
    }

    const int cvt_blocks = (int)(((size_t)NPTS * CIN + 255) / 256);
    k_convert<<<cvt_blocks, 256>>>(feats, w1, w3);

    k1_expand<<<dim3((NPTS + 127) / 128, CHID / 64), 256>>>(b1, s1);
    k23_fused<<<(NPTS + 63) / 64, 256, SMEM_K23>>>(nbr, w2, b2, s2,
                                                   feats, b3, s3, smain, sres, out);
}